// round 4
// baseline (speedup 1.0000x reference)
#include <cuda_runtime.h>
#include <cstdint>

#define BATCH   32
#define NA      9
#define HW      4096
#define NPROP   (HW*NA)          // 36864
#define NVEC    (NPROP/4)        // 9216 float4 per batch
#define TOPK    300
#define OUTC    66
#define CAP     4096

// key for score >= 2.0f  (P(N(0,1) > 2) * 36864 ~ 840 candidates/batch)
#define THR_FAST 0xC0000000u

// Anchor (w,h) table; centers are always (8+16*gx, 8+16*gy)
__constant__ float c_aw[9] = {92.f,184.f,368.f,64.f,128.f,256.f,44.f,88.f,176.f};
__constant__ float c_ah[9] = {48.f,96.f,192.f,64.f,128.f,256.f,88.f,176.f,352.f};

// decode feed: per batch, ascending-n order; packed = n | (rank<<16)
__device__ unsigned g_dec[BATCH * TOPK];

__device__ __forceinline__ unsigned f2key(float s) {
    unsigned u = __float_as_uint(s);
    return (u & 0x80000000u) ? ~u : (u | 0x80000000u);
}

// ---------------------------------------------------------------------------
// Exact top-k, one CTA per batch.
// Fast path: single read pass, fixed-threshold compact (no histogram).
// Fallback (any input where the fixed cut fails): 4096-bin histogram select.
// Then exact rank-by-count over the candidates (unique 64-bit keys ->
// reproduces jax.lax.top_k tie-breaking exactly).
// ---------------------------------------------------------------------------
__global__ __launch_bounds__(1024, 1)
void topk_kernel(const float* __restrict__ scores_in, float* __restrict__ out)
{
    __shared__ unsigned long long cand[CAP];     // 32 KB
    __shared__ unsigned hist[4096];              // 16 KB (fallback only)
    __shared__ unsigned sel_n[TOPK];
    __shared__ unsigned wsum[32], wpre[32];
    __shared__ unsigned s_thr;
    __shared__ int s_cnt;

    const int b = blockIdx.x;
    const int tid = threadIdx.x;
    const unsigned lane = tid & 31u;
    const int warp = tid >> 5;

    if (tid == 0) s_cnt = 0;
    __syncthreads();

    const float4* sp = (const float4*)(scores_in + (size_t)b * 18 * HW + (size_t)NA * HW);

    // ---- fast path: one pass, fixed threshold ----
    #pragma unroll 3
    for (int i = tid; i < NVEC; i += 1024) {
        float4 v = sp[i];
        float vv[4] = {v.x, v.y, v.z, v.w};
        #pragma unroll
        for (int j = 0; j < 4; j++) {
            unsigned k = f2key(vv[j]);
            if (k >= THR_FAST) {
                int idx = 4 * i + j;              // memory order: a*4096 + hw
                int a = idx >> 12, hw = idx & 4095;
                int n = hw * 9 + a;               // jax flat order
                int pos = atomicAdd(&s_cnt, 1);
                if (pos < CAP)
                    cand[pos] = ((unsigned long long)k << 32) | (unsigned)(~n);
            }
        }
    }
    __syncthreads();
    int C = s_cnt;

    // ---- fallback: exact histogram select (rare; correctness safety net) ----
    if (C < TOPK || C > CAP) {
        #pragma unroll
        for (int i = tid; i < 4096; i += 1024) hist[i] = 0;
        if (tid == 0) s_cnt = 0;
        __syncthreads();
        #pragma unroll 3
        for (int i = tid; i < NVEC; i += 1024) {
            float4 v = sp[i];
            atomicAdd(&hist[f2key(v.x) >> 20], 1u);
            atomicAdd(&hist[f2key(v.y) >> 20], 1u);
            atomicAdd(&hist[f2key(v.z) >> 20], 1u);
            atomicAdd(&hist[f2key(v.w) >> 20], 1u);
        }
        __syncthreads();
        // parallel suffix scan from the top: thread t owns bins [4095-4t..]
        const int bhi = 4095 - 4 * tid;
        unsigned h0 = hist[bhi],     h1 = hist[bhi - 1];
        unsigned h2 = hist[bhi - 2], h3 = hist[bhi - 3];
        unsigned s = h0 + h1 + h2 + h3;
        unsigned incl = s;
        #pragma unroll
        for (int o = 1; o < 32; o <<= 1) {
            unsigned v = __shfl_up_sync(0xFFFFFFFFu, incl, o);
            if (lane >= o) incl += v;
        }
        if (lane == 31) wsum[warp] = incl;
        __syncthreads();
        if (warp == 0) {
            unsigned w = wsum[lane];
            unsigned wi = w;
            #pragma unroll
            for (int o = 1; o < 32; o <<= 1) {
                unsigned v = __shfl_up_sync(0xFFFFFFFFu, wi, o);
                if (lane >= o) wi += v;
            }
            wpre[lane] = wi - w;
        }
        __syncthreads();
        {
            unsigned c = wpre[warp] + (incl - s);
            unsigned hh[4] = {h0, h1, h2, h3};
            #pragma unroll
            for (int j = 0; j < 4; j++) {
                if (c < TOPK && c + hh[j] >= TOPK)
                    s_thr = ((unsigned)(bhi - j)) << 20;
                c += hh[j];
            }
        }
        __syncthreads();
        const unsigned thr = s_thr;
        #pragma unroll 3
        for (int i = tid; i < NVEC; i += 1024) {
            float4 v = sp[i];
            float vv[4] = {v.x, v.y, v.z, v.w};
            #pragma unroll
            for (int j = 0; j < 4; j++) {
                unsigned k = f2key(vv[j]);
                if (k >= thr) {
                    int idx = 4 * i + j;
                    int a = idx >> 12, hw = idx & 4095;
                    int n = hw * 9 + a;
                    int pos = atomicAdd(&s_cnt, 1);
                    if (pos < CAP)
                        cand[pos] = ((unsigned long long)k << 32) | (unsigned)(~n);
                }
            }
        }
        __syncthreads();
        C = min(s_cnt, CAP);
    }

    // ---- exact rank by counting ----
    for (int i = tid; i < C; i += 1024) {
        const unsigned long long me = cand[i];
        int r = 0;
        for (int j = 0; j < C; j++) r += (cand[j] > me);   // smem broadcast
        if (r < TOPK) {
            unsigned n = (unsigned)(~(unsigned)me) & 0xFFFFu;
            sel_n[r] = n;
            unsigned k32 = (unsigned)(me >> 32);
            unsigned u = (k32 & 0x80000000u) ? (k32 & 0x7FFFFFFFu) : ~k32;
            size_t row = ((size_t)b * TOPK + r) * OUTC;
            out[row + 0] = (float)b;
            out[row + OUTC - 1] = __uint_as_float(u);
        }
    }
    __syncthreads();

    // decode order: ascending flat index n (DRAM/L2 locality for the gather)
    if (tid < TOPK) {
        unsigned n = sel_n[tid];
        int o = 0;
        for (int j = 0; j < TOPK; j++) o += (sel_n[j] < n);
        g_dec[b * TOPK + o] = n | ((unsigned)tid << 16);
    }
}

// ---------------------------------------------------------------------------
// Decode: 512 threads/block; each 64-thread group serves 4 proposals
// (4 independent scattered loads per thread -> MLP=4, single wave).
// ---------------------------------------------------------------------------
__global__ __launch_bounds__(512)
void decode_kernel(const float* __restrict__ bbox,
                   const float* __restrict__ im_info,
                   float* __restrict__ out)
{
    const int tid = threadIdx.x;
    const int b = blockIdx.y;
    const int g = tid >> 6;                 // group 0..7
    const int k = tid & 63;                 // coordinate within proposal
    const int j0 = (blockIdx.x * 8 + g) * 4;
    const unsigned base = (tid & 31u) & ~3u;

    const float xmax = im_info[b * 3 + 1] - 1.0f;
    const float ymax = im_info[b * 3 + 0] - 1.0f;

    unsigned pk[4];
    float d[4];
    #pragma unroll
    for (int q = 0; q < 4; q++) {
        int j = j0 + q;
        pk[q] = g_dec[b * TOPK + (j < TOPK ? j : 0)];
    }
    #pragma unroll
    for (int q = 0; q < 4; q++) {
        int n = pk[q] & 0xFFFFu;
        int a = n % 9, hw = n / 9;
        d[q] = __ldcs(&bbox[((size_t)b * 576 + a * 64 + k) * HW + hw]);
    }

    #pragma unroll
    for (int q = 0; q < 4; q++) {
        const int j = j0 + q;
        const int n = pk[q] & 0xFFFFu;
        const int rank = pk[q] >> 16;
        const int a = n % 9, hw = n / 9;
        const float w  = c_aw[a];
        const float h  = c_ah[a];
        const float cx = 8.0f + 16.0f * (float)(hw & 63);
        const float cy = 8.0f + 16.0f * (float)(hw >> 6);

        const float d0 = __shfl_sync(0xFFFFFFFFu, d[q], base + 0);
        const float d1 = __shfl_sync(0xFFFFFFFFu, d[q], base + 1);
        const float d2 = __shfl_sync(0xFFFFFFFFu, d[q], base + 2);
        const float d3 = __shfl_sync(0xFFFFFFFFu, d[q], base + 3);

        const float pcx = d0 * w + cx;
        const float pcy = d1 * h + cy;
        const float pw  = expf(d2) * w;
        const float ph  = expf(d3) * h;

        float v;
        switch (k & 3) {
            case 0: v = fminf(fmaxf(pcx - 0.5f * pw, 0.0f), xmax); break;
            case 1: v = fminf(fmaxf(pcy - 0.5f * ph, 0.0f), ymax); break;
            case 2: v = fminf(fmaxf(pcx + 0.5f * pw, 0.0f), xmax); break;
            default: v = fminf(fmaxf(pcy + 0.5f * ph, 0.0f), ymax); break;
        }

        if (j < TOPK)
            out[((size_t)b * TOPK + rank) * OUTC + 1 + k] = v;
    }
}

extern "C" void kernel_launch(void* const* d_in, const int* in_sizes, int n_in,
                              void* d_out, int out_size)
{
    const float* scores  = (const float*)d_in[0];  // (32,18,64,64)
    const float* bbox    = (const float*)d_in[1];  // (32,576,64,64)
    const float* im_info = (const float*)d_in[2];  // (32,3)
    float* out = (float*)d_out;                    // (32,300,66)

    topk_kernel<<<BATCH, 1024>>>(scores, out);
    decode_kernel<<<dim3((TOPK + 31) / 32, BATCH), 512>>>(bbox, im_info, out);
}